// round 1
// baseline (speedup 1.0000x reference)
#include <cuda_runtime.h>
#include <math.h>
#include <float.h>

#define NN   20000
#define EE   340000
#define DD   128
#define CC1  256

// ---- output layout (element offsets into float* d_out) ----
#define OFF_S1  0
#define OFF_S2  (NN*CC1)                 // 5,120,000
#define OFF_A1  (OFF_S2 + 256*32)        // 5,128,192
#define OFF_E3  (OFF_A1 + 32)            // 5,128,224
#define OFF_X1  (OFF_E3 + NN*DD)         // 7,688,224
#define OFF_X2  (OFF_X1 + 256*128)       // 7,720,992
#define OFF_E0  (OFF_X2 + 32*128)        // 7,725,088

// ---- scratch (device globals; no allocation allowed) ----
__device__ float g_zf[NN*DD];
__device__ float g_x[NN*DD];
__device__ float g_z1lin[NN*DD];
__device__ float g_z1[NN*DD];
__device__ float g_zgat[NN*CC1];
__device__ float g_asrc[NN];
__device__ float g_adst[NN];
__device__ int   g_deg[NN];
__device__ int   g_off[NN+1];
__device__ int   g_cur[NN];
__device__ int   g_csrc[EE];
__device__ float g_x1[CC1*DD];

// ============================ graph build ============================
__global__ void k_init() {
    int i = blockIdx.x*blockDim.x + threadIdx.x;
    if (i < NN) g_deg[i] = 0;
    if (i < CC1*DD) g_x1[i] = 0.0f;
}

__global__ void k_count(const int* __restrict__ dst) {
    int e = blockIdx.x*blockDim.x + threadIdx.x;
    if (e < EE) atomicAdd(&g_deg[dst[e]], 1);
}

__global__ void k_scan() {   // single block, 1024 threads
    const int CH = (NN + 1023) / 1024;
    __shared__ int sh[1024];
    int t = threadIdx.x;
    int start = t*CH;
    int end = min(start + CH, NN);
    int s = 0;
    for (int i = start; i < end; i++) s += g_deg[i];
    sh[t] = s; __syncthreads();
    for (int off = 1; off < 1024; off <<= 1) {
        int v = 0;
        if (t >= off) v = sh[t-off];
        __syncthreads();
        if (t >= off) sh[t] += v;
        __syncthreads();
    }
    int run = (t == 0) ? 0 : sh[t-1];
    for (int i = start; i < end; i++) {
        g_off[i] = run; g_cur[i] = run;
        run += g_deg[i];
    }
    if (t == 1023) g_off[NN] = run;
}

__global__ void k_fill(const int* __restrict__ src, const int* __restrict__ dst) {
    int e = blockIdx.x*blockDim.x + threadIdx.x;
    if (e < EE) {
        int p = atomicAdd(&g_cur[dst[e]], 1);
        g_csrc[p] = src[e];
    }
}

// ============================ SGEMM 128x128x8 ============================
// C[M,Nt] = A[M,K] @ B[K,Nt] + bias[Nt].  K multiple of 8, Nt multiple of 128.
__global__ __launch_bounds__(256) void k_sgemm(
    const float* __restrict__ A, const float* __restrict__ B,
    const float* __restrict__ bias, float* __restrict__ C,
    int M, int Nt, int K)
{
    __shared__ float As[8][128];
    __shared__ float Bs[8][128];
    int tid  = threadIdx.x;
    int row0 = blockIdx.y*128, col0 = blockIdx.x*128;
    int tr = tid/16, tc = tid%16;
    float acc[8][8];
    #pragma unroll
    for (int i = 0; i < 8; i++)
        #pragma unroll
        for (int j = 0; j < 8; j++) acc[i][j] = 0.0f;

    int aRow = tid/2, aCol = (tid%2)*4;     // A: 128x8 tile
    int bRow = tid/32, bCol = (tid%32)*4;   // B: 8x128 tile

    for (int k0 = 0; k0 < K; k0 += 8) {
        float4 av;
        int gr = row0 + aRow;
        if (gr < M) av = *(const float4*)(A + (size_t)gr*K + k0 + aCol);
        else        av = make_float4(0.f,0.f,0.f,0.f);
        As[aCol+0][aRow] = av.x; As[aCol+1][aRow] = av.y;
        As[aCol+2][aRow] = av.z; As[aCol+3][aRow] = av.w;
        float4 bv = *(const float4*)(B + (size_t)(k0+bRow)*Nt + col0 + bCol);
        *(float4*)&Bs[bRow][bCol] = bv;
        __syncthreads();
        #pragma unroll
        for (int kk = 0; kk < 8; kk++) {
            float ra[8], rb[8];
            *(float4*)(ra)   = *(float4*)&As[kk][tr*8];
            *(float4*)(ra+4) = *(float4*)&As[kk][tr*8+4];
            *(float4*)(rb)   = *(float4*)&Bs[kk][tc*8];
            *(float4*)(rb+4) = *(float4*)&Bs[kk][tc*8+4];
            #pragma unroll
            for (int i = 0; i < 8; i++)
                #pragma unroll
                for (int j = 0; j < 8; j++)
                    acc[i][j] = fmaf(ra[i], rb[j], acc[i][j]);
        }
        __syncthreads();
    }
    #pragma unroll
    for (int i = 0; i < 8; i++) {
        int gr = row0 + tr*8 + i;
        if (gr >= M) continue;
        int gc = col0 + tc*8;
        float4 o0, o1;
        o0.x = acc[i][0] + bias[gc+0]; o0.y = acc[i][1] + bias[gc+1];
        o0.z = acc[i][2] + bias[gc+2]; o0.w = acc[i][3] + bias[gc+3];
        o1.x = acc[i][4] + bias[gc+4]; o1.y = acc[i][5] + bias[gc+5];
        o1.z = acc[i][6] + bias[gc+6]; o1.w = acc[i][7] + bias[gc+7];
        *(float4*)(C + (size_t)gr*Nt + gc)     = o0;
        *(float4*)(C + (size_t)gr*Nt + gc + 4) = o1;
    }
}

// ============================ segment mean (warp/node) ============================
template<bool NORM>
__global__ __launch_bounds__(256) void k_segmean(
    const float* __restrict__ zin, float* __restrict__ out, float* __restrict__ out2)
{
    int node = blockIdx.x*8 + (threadIdx.x >> 5);
    if (node >= NN) return;
    int lane = threadIdx.x & 31;
    int e0 = g_off[node], e1 = g_off[node+1];
    float4 acc = make_float4(0.f,0.f,0.f,0.f);
    for (int j = e0; j < e1; j++) {
        int s = g_csrc[j];
        float4 v = *(const float4*)(zin + (size_t)s*DD + lane*4);
        acc.x += v.x; acc.y += v.y; acc.z += v.z; acc.w += v.w;
    }
    float inv = 1.0f / (float)(e1 - e0);
    acc.x *= inv; acc.y *= inv; acc.z *= inv; acc.w *= inv;
    if (NORM) {
        float ss = acc.x*acc.x + acc.y*acc.y + acc.z*acc.z + acc.w*acc.w;
        #pragma unroll
        for (int o = 16; o > 0; o >>= 1) ss += __shfl_xor_sync(0xffffffffu, ss, o);
        float nrm = sqrtf(ss);
        float r = 1.0f / fmaxf(nrm, 1e-12f);
        acc.x *= r; acc.y *= r; acc.z *= r; acc.w *= r;
    }
    *(float4*)(out + (size_t)node*DD + lane*4) = acc;
    if (out2) *(float4*)(out2 + (size_t)node*DD + lane*4) = acc;
}

// ============================ attention scalars ============================
__global__ __launch_bounds__(256) void k_attvec(const float* __restrict__ attW) {
    int node = blockIdx.x*8 + (threadIdx.x >> 5);
    if (node >= NN) return;
    int lane = threadIdx.x & 31;
    float s_src = 0.f, s_dst = 0.f;
    #pragma unroll
    for (int c = lane; c < CC1; c += 32) {
        float z = g_zgat[(size_t)node*CC1 + c];
        s_src = fmaf(z, attW[c], s_src);
        s_dst = fmaf(z, attW[CC1 + c], s_dst);
    }
    #pragma unroll
    for (int o = 16; o > 0; o >>= 1) {
        s_src += __shfl_xor_sync(0xffffffffu, s_src, o);
        s_dst += __shfl_xor_sync(0xffffffffu, s_dst, o);
    }
    if (lane == 0) { g_asrc[node] = s_src; g_adst[node] = s_dst; }
}

// ============================ GAT + row softmax (block/node) ============================
__global__ __launch_bounds__(256) void k_gat(const float* __restrict__ attb,
                                             float* __restrict__ s1out)
{
    __shared__ float red[256];
    __shared__ float salpha[256];
    __shared__ int   ssrc[256];
    int node = blockIdx.x;
    int c = threadIdx.x;
    int e0 = g_off[node], e1 = g_off[node+1];
    float ad = g_adst[node] + attb[0];

    // phase A: segment max of leaky_relu(e)
    float lm = -FLT_MAX;
    for (int j = e0 + c; j < e1; j += 256) {
        float e = g_asrc[g_csrc[j]] + ad;
        e = (e > 0.f) ? e : 0.01f*e;
        lm = fmaxf(lm, e);
    }
    red[c] = lm; __syncthreads();
    #pragma unroll
    for (int st = 128; st > 0; st >>= 1) {
        if (c < st) red[c] = fmaxf(red[c], red[c+st]);
        __syncthreads();
    }
    float m = red[0]; __syncthreads();

    // phase B: alpha + weighted accumulation (chunked)
    float denom_loc = 0.f, acc = 0.f;
    for (int base = e0; base < e1; base += 256) {
        int cnt = min(256, e1 - base);
        float a = 0.f; int s = 0;
        if (c < cnt) {
            s = g_csrc[base + c];
            float e = g_asrc[s] + ad;
            e = (e > 0.f) ? e : 0.01f*e;
            a = __expf(e - m);
            denom_loc += a;
        }
        ssrc[c] = s; salpha[c] = a;
        __syncthreads();
        for (int j = 0; j < cnt; j++)
            acc = fmaf(salpha[j], g_zgat[(size_t)ssrc[j]*CC1 + c], acc);
        __syncthreads();
    }
    red[c] = denom_loc; __syncthreads();
    #pragma unroll
    for (int st = 128; st > 0; st >>= 1) {
        if (c < st) red[c] += red[c+st];
        __syncthreads();
    }
    float val = acc / red[0]; __syncthreads();

    // row softmax over 256 channels
    red[c] = val; __syncthreads();
    #pragma unroll
    for (int st = 128; st > 0; st >>= 1) {
        if (c < st) red[c] = fmaxf(red[c], red[c+st]);
        __syncthreads();
    }
    float vm = red[0]; __syncthreads();
    float ex = __expf(val - vm);
    red[c] = ex; __syncthreads();
    #pragma unroll
    for (int st = 128; st > 0; st >>= 1) {
        if (c < st) red[c] += red[c+st];
        __syncthreads();
    }
    s1out[(size_t)node*CC1 + c] = ex / red[0];
}

// ============================ x1 = s1^T @ z1 (split-K, atomic) ============================
#define SPLITS 80
__global__ __launch_bounds__(256) void k_at_b(const float* __restrict__ S,
                                              const float* __restrict__ Z)
{
    __shared__ float sS[16][64];
    __shared__ float sZ[16][128];
    int chunk = blockIdx.x;
    int k_begin = (int)((long long)NN * chunk / SPLITS);
    int k_end   = (int)((long long)NN * (chunk+1) / SPLITS);
    int m0 = blockIdx.y * 64;
    int tid = threadIdx.x;
    int tr = tid/16, tc = tid%16;   // rows tr*4..+3 of 64, cols tc*8..+7 of 128
    float acc[4][8];
    #pragma unroll
    for (int i = 0; i < 4; i++)
        #pragma unroll
        for (int j = 0; j < 8; j++) acc[i][j] = 0.f;

    for (int k0 = k_begin; k0 < k_end; k0 += 16) {
        int kc = min(16, k_end - k0);
        // load S slice [16][64]
        {
            int r = tid/16, c4 = (tid%16)*4;
            float4 v = make_float4(0.f,0.f,0.f,0.f);
            if (r < kc) v = *(const float4*)(S + (size_t)(k0+r)*CC1 + m0 + c4);
            *(float4*)&sS[r][c4] = v;
        }
        // load Z slice [16][128]
        #pragma unroll
        for (int half = 0; half < 2; half++) {
            int r = tid/32 + half*8, c4 = (tid%32)*4;
            float4 v = make_float4(0.f,0.f,0.f,0.f);
            if (r < kc) v = *(const float4*)(Z + (size_t)(k0+r)*DD + c4);
            *(float4*)&sZ[r][c4] = v;
        }
        __syncthreads();
        #pragma unroll
        for (int kk = 0; kk < 16; kk++) {
            float ra[4], rb[8];
            *(float4*)(ra)   = *(float4*)&sS[kk][tr*4];
            *(float4*)(rb)   = *(float4*)&sZ[kk][tc*8];
            *(float4*)(rb+4) = *(float4*)&sZ[kk][tc*8+4];
            #pragma unroll
            for (int i = 0; i < 4; i++)
                #pragma unroll
                for (int j = 0; j < 8; j++)
                    acc[i][j] = fmaf(ra[i], rb[j], acc[i][j]);
        }
        __syncthreads();
    }
    #pragma unroll
    for (int i = 0; i < 4; i++)
        #pragma unroll
        for (int j = 0; j < 8; j++)
            atomicAdd(&g_x1[(m0 + tr*4 + i)*DD + tc*8 + j], acc[i][j]);
}

// ============================ analytic coarse tail ============================
__global__ __launch_bounds__(256) void k_tail(
    const float* __restrict__ We2, const float* __restrict__ be2,
    const float* __restrict__ Wa2, const float* __restrict__ ba2,
    float* __restrict__ out)
{
    __shared__ float meanx1[128];
    __shared__ float meanvec[128];
    __shared__ float s2row[32];
    int t = threadIdx.x;

    // copy x1 to output
    for (int i = t; i < CC1*DD; i += 256) out[OFF_X1 + i] = g_x1[i];

    // column mean of x1 over 256 rows
    if (t < 128) {
        float s = 0.f;
        for (int j = 0; j < CC1; j++) s += g_x1[j*DD + t];
        meanx1[t] = s * (1.0f/256.0f);
    }
    __syncthreads();
    // meanvec = meanx1 @ We2 + be2
    if (t < 128) {
        float s = 0.f;
        for (int e = 0; e < 128; e++) s = fmaf(meanx1[e], We2[e*128 + t], s);
        meanvec[t] = s + be2[t];
    }
    __syncthreads();
    // v = meanvec @ Wa2 + ba2, softmax over 32 (warp 0)
    if (t < 32) {
        float s = 0.f;
        for (int d = 0; d < 128; d++) s = fmaf(meanvec[d], Wa2[d*32 + t], s);
        float v = s + ba2[t];
        float mx = v;
        #pragma unroll
        for (int o = 16; o > 0; o >>= 1) mx = fmaxf(mx, __shfl_xor_sync(0xffffffffu, mx, o));
        float ex = __expf(v - mx);
        float sm = ex;
        #pragma unroll
        for (int o = 16; o > 0; o >>= 1) sm += __shfl_xor_sync(0xffffffffu, sm, o);
        s2row[t] = ex / sm;
    }
    __syncthreads();
    // s2: 256 identical rows
    for (int i = t; i < 256*32; i += 256) out[OFF_S2 + i] = s2row[i & 31];
    // assign1: ones
    if (t < 32) out[OFF_A1 + t] = 1.0f;
    // x2[k,d] = 256 * s2row[k] * meanvec[d]
    for (int i = t; i < 32*128; i += 256)
        out[OFF_X2 + i] = 256.0f * s2row[i >> 7] * meanvec[i & 127];
    // embed0 = (1/16) * sum(meanvec)
    if (t == 0) {
        float s = 0.f;
        for (int d = 0; d < 128; d++) s += meanvec[d];
        out[OFF_E0] = s * (1.0f/16.0f);
    }
}

// ============================ launch ============================
extern "C" void kernel_launch(void* const* d_in, const int* in_sizes, int n_in,
                              void* d_out, int out_size)
{
    const float* feature = (const float*)d_in[0];
    const int*   eidx    = (const int*)d_in[1];
    const int*   src     = eidx;
    const int*   dst     = eidx + EE;
    const float* Wf   = (const float*)d_in[2];
    const float* bf   = (const float*)d_in[3];
    const float* We1  = (const float*)d_in[4];
    const float* be1  = (const float*)d_in[5];
    const float* Wa1  = (const float*)d_in[6];
    const float* ba1  = (const float*)d_in[7];
    const float* attW1 = (const float*)d_in[8];
    const float* attb1 = (const float*)d_in[9];
    const float* We2  = (const float*)d_in[10];
    const float* be2  = (const float*)d_in[11];
    const float* Wa2  = (const float*)d_in[12];
    const float* ba2  = (const float*)d_in[13];
    float* out = (float*)d_out;

    float* g_zf_p; float* g_x_p; float* g_z1lin_p; float* g_z1_p; float* g_zgat_p;
    cudaGetSymbolAddress((void**)&g_zf_p, g_zf);
    cudaGetSymbolAddress((void**)&g_x_p, g_x);
    cudaGetSymbolAddress((void**)&g_z1lin_p, g_z1lin);
    cudaGetSymbolAddress((void**)&g_z1_p, g_z1);
    cudaGetSymbolAddress((void**)&g_zgat_p, g_zgat);

    // graph build
    k_init<<<(CC1*DD + 255)/256, 256>>>();
    k_count<<<(EE + 255)/256, 256>>>(dst);
    k_scan<<<1, 1024>>>();
    k_fill<<<(EE + 255)/256, 256>>>(src, dst);

    // zf = feature @ Wf + bf
    k_sgemm<<<dim3(1, (NN+127)/128), 256>>>(feature, Wf, bf, g_zf_p, NN, 128, 128);
    // x = normalize(segmean(zf)); embed3 = x
    k_segmean<true><<<(NN+7)/8, 256>>>(g_zf_p, g_x_p, out + OFF_E3);
    // z1lin = x @ We1 + be1
    k_sgemm<<<dim3(1, (NN+127)/128), 256>>>(g_x_p, We1, be1, g_z1lin_p, NN, 128, 128);
    // z1 = segmean(z1lin)
    k_segmean<false><<<(NN+7)/8, 256>>>(g_z1lin_p, g_z1_p, (float*)0);
    // zgat = z1 @ Wa1 + ba1
    k_sgemm<<<dim3(2, (NN+127)/128), 256>>>(g_z1_p, Wa1, ba1, g_zgat_p, NN, 256, 128);
    // attention scalars
    k_attvec<<<(NN+7)/8, 256>>>(attW1);
    // GAT + row softmax -> s1 (written directly to output)
    k_gat<<<NN, 256>>>(attb1, out + OFF_S1);
    // x1 = s1^T @ z1 (split-K atomics into g_x1)
    k_at_b<<<dim3(SPLITS, 4), 256>>>(out + OFF_S1, g_z1_p);
    // analytic coarse level: s2, assign1, x2, embed0, x1 copy
    k_tail<<<1, 256>>>(We2, be2, Wa2, ba2, out);
}

// round 2
// speedup vs baseline: 1.0903x; 1.0903x over previous
#include <cuda_runtime.h>
#include <math.h>
#include <float.h>

#define NN   20000
#define EE   340000
#define DD   128
#define CC1  256

// ---- output layout (element offsets into float* d_out) ----
#define OFF_S1  0
#define OFF_S2  (NN*CC1)
#define OFF_A1  (OFF_S2 + 256*32)
#define OFF_E3  (OFF_A1 + 32)
#define OFF_X1  (OFF_E3 + NN*DD)
#define OFF_X2  (OFF_X1 + 256*128)
#define OFF_E0  (OFF_X2 + 32*128)

// ---- scratch ----
__device__ float g_mf[NN*DD];
__device__ float g_x[NN*DD];
__device__ float g_m2[NN*DD];
__device__ float g_magg[NN*DD];
__device__ float g_asrc[NN];
__device__ float g_adst[NN];
__device__ int   g_deg[NN];
__device__ int   g_off[NN+1];
__device__ int   g_cur[NN];
__device__ int   g_csrc[EE];
__device__ float g_Wcomb[DD*CC1];   // 128x256
__device__ float g_bcomb[CC1];
__device__ float g_us[DD];
__device__ float g_ud[DD];
__device__ float g_cs[2];
__device__ float g_T[CC1*DD];       // s1^T @ m2  (256x128)
__device__ float g_colsum[CC1];

// ============================ graph build ============================
__global__ void k_init() {
    int i = blockIdx.x*blockDim.x + threadIdx.x;
    if (i < NN) g_deg[i] = 0;
    if (i < CC1*DD) g_T[i] = 0.0f;
    if (i < CC1) g_colsum[i] = 0.0f;
}

__global__ void k_count(const int* __restrict__ dst) {
    int e = blockIdx.x*blockDim.x + threadIdx.x;
    if (e < EE) atomicAdd(&g_deg[dst[e]], 1);
}

__global__ void k_scan() {
    const int CH = (NN + 1023) / 1024;
    __shared__ int sh[1024];
    int t = threadIdx.x;
    int start = t*CH, end = min(start + CH, NN);
    int s = 0;
    for (int i = start; i < end; i++) s += g_deg[i];
    sh[t] = s; __syncthreads();
    for (int off = 1; off < 1024; off <<= 1) {
        int v = 0;
        if (t >= off) v = sh[t-off];
        __syncthreads();
        if (t >= off) sh[t] += v;
        __syncthreads();
    }
    int run = (t == 0) ? 0 : sh[t-1];
    for (int i = start; i < end; i++) {
        g_off[i] = run; g_cur[i] = run;
        run += g_deg[i];
    }
    if (t == 1023) g_off[NN] = run;
}

__global__ void k_fill(const int* __restrict__ src, const int* __restrict__ dst) {
    int e = blockIdx.x*blockDim.x + threadIdx.x;
    if (e < EE) {
        int p = atomicAdd(&g_cur[dst[e]], 1);
        g_csrc[p] = src[e];
    }
}

// ============================ weight folding ============================
// blocks 0..127: row e of W_comb = We1[e,:] @ Wa1  (Wa1: 128x256)
// block 128: t_s/t_d = Wa1@aW halves; u_s/u_d = We1@t; b_comb; c_s/c_d
__global__ __launch_bounds__(256) void k_fold(
    const float* __restrict__ We1, const float* __restrict__ be1,
    const float* __restrict__ Wa1, const float* __restrict__ ba1,
    const float* __restrict__ attW)
{
    int b = blockIdx.x, t = threadIdx.x;
    if (b < 128) {
        __shared__ float sWe[128];
        if (t < 128) sWe[t] = We1[b*128 + t];
        __syncthreads();
        float acc = 0.f;
        #pragma unroll 8
        for (int k = 0; k < 128; k++) acc = fmaf(sWe[k], Wa1[k*256 + t], acc);
        g_Wcomb[b*256 + t] = acc;
    } else {
        __shared__ float ts[128], td[128], bc[256];
        if (t < 128) {
            float s1v = 0.f, s2v = 0.f;
            for (int c = 0; c < 256; c++) {
                float w = Wa1[t*256 + c];
                s1v = fmaf(w, attW[c], s1v);
                s2v = fmaf(w, attW[256 + c], s2v);
            }
            ts[t] = s1v; td[t] = s2v;
        }
        {   // b_comb
            float s = 0.f;
            for (int e = 0; e < 128; e++) s = fmaf(be1[e], Wa1[e*256 + t], s);
            bc[t] = s + ba1[t];
            g_bcomb[t] = bc[t];
        }
        __syncthreads();
        if (t < 128) {
            float u1 = 0.f, u2 = 0.f;
            for (int e = 0; e < 128; e++) {
                float w = We1[t*128 + e];
                u1 = fmaf(w, ts[e], u1);
                u2 = fmaf(w, td[e], u2);
            }
            g_us[t] = u1; g_ud[t] = u2;
        }
        if (t == 0) {
            float c1v = 0.f, c2v = 0.f;
            for (int c = 0; c < 256; c++) {
                c1v = fmaf(bc[c], attW[c], c1v);
                c2v = fmaf(bc[c], attW[256 + c], c2v);
            }
            g_cs[0] = c1v; g_cs[1] = c2v;
        }
    }
}

// ============================ segment mean (warp/node) ============================
// NORM: L2-normalize row. DOTS: also emit a_src/a_dst via folded attention vectors.
template<bool NORM, bool DOTS>
__global__ __launch_bounds__(256) void k_segmean(
    const float* __restrict__ zin, float* __restrict__ out, float* __restrict__ out2)
{
    int node = blockIdx.x*8 + (threadIdx.x >> 5);
    if (node >= NN) return;
    int lane = threadIdx.x & 31;
    int e0 = g_off[node], e1 = g_off[node+1];
    float4 acc = make_float4(0.f,0.f,0.f,0.f);
    int j = e0;
    for (; j + 2 <= e1; j += 2) {
        int s0 = g_csrc[j], s1i = g_csrc[j+1];
        float4 v0 = *(const float4*)(zin + (size_t)s0*DD + lane*4);
        float4 v1 = *(const float4*)(zin + (size_t)s1i*DD + lane*4);
        acc.x += v0.x + v1.x; acc.y += v0.y + v1.y;
        acc.z += v0.z + v1.z; acc.w += v0.w + v1.w;
    }
    if (j < e1) {
        int s0 = g_csrc[j];
        float4 v0 = *(const float4*)(zin + (size_t)s0*DD + lane*4);
        acc.x += v0.x; acc.y += v0.y; acc.z += v0.z; acc.w += v0.w;
    }
    float inv = 1.0f / (float)(e1 - e0);
    acc.x *= inv; acc.y *= inv; acc.z *= inv; acc.w *= inv;
    if (NORM) {
        float ss = acc.x*acc.x + acc.y*acc.y + acc.z*acc.z + acc.w*acc.w;
        #pragma unroll
        for (int o = 16; o > 0; o >>= 1) ss += __shfl_xor_sync(0xffffffffu, ss, o);
        float r = 1.0f / fmaxf(sqrtf(ss), 1e-12f);
        acc.x *= r; acc.y *= r; acc.z *= r; acc.w *= r;
    }
    *(float4*)(out + (size_t)node*DD + lane*4) = acc;
    if (out2) *(float4*)(out2 + (size_t)node*DD + lane*4) = acc;
    if (DOTS) {
        float4 us4 = *(const float4*)(g_us + lane*4);
        float4 ud4 = *(const float4*)(g_ud + lane*4);
        float as = acc.x*us4.x + acc.y*us4.y + acc.z*us4.z + acc.w*us4.w;
        float ad = acc.x*ud4.x + acc.y*ud4.y + acc.z*ud4.z + acc.w*ud4.w;
        #pragma unroll
        for (int o = 16; o > 0; o >>= 1) {
            as += __shfl_xor_sync(0xffffffffu, as, o);
            ad += __shfl_xor_sync(0xffffffffu, ad, o);
        }
        if (lane == 0) { g_asrc[node] = as + g_cs[0]; g_adst[node] = ad + g_cs[1]; }
    }
}

// ============================ GEMM 128x128 + L2-norm epilogue ============================
// x = normalize(A@W + bias). M=NN, N=128, K=128.
__global__ __launch_bounds__(256) void k_gemm_norm(
    const float* __restrict__ A, const float* __restrict__ B,
    const float* __restrict__ bias, float* __restrict__ C, float* __restrict__ C2)
{
    __shared__ float As[8][128];
    __shared__ float Bs[8][128];
    __shared__ float red[128][16];
    int tid = threadIdx.x;
    int row0 = blockIdx.x*128;
    int tr = tid/16, tc = tid%16;
    float acc[8][8];
    #pragma unroll
    for (int i = 0; i < 8; i++)
        #pragma unroll
        for (int jj = 0; jj < 8; jj++) acc[i][jj] = 0.0f;

    int aRow = tid/2, aCol = (tid%2)*4;
    int bRow = tid/32, bCol = (tid%32)*4;

    for (int k0 = 0; k0 < 128; k0 += 8) {
        float4 av = make_float4(0.f,0.f,0.f,0.f);
        int gr = row0 + aRow;
        if (gr < NN) av = *(const float4*)(A + (size_t)gr*128 + k0 + aCol);
        As[aCol+0][aRow] = av.x; As[aCol+1][aRow] = av.y;
        As[aCol+2][aRow] = av.z; As[aCol+3][aRow] = av.w;
        *(float4*)&Bs[bRow][bCol] = *(const float4*)(B + (size_t)(k0+bRow)*128 + bCol);
        __syncthreads();
        #pragma unroll
        for (int kk = 0; kk < 8; kk++) {
            float ra[8], rb[8];
            *(float4*)(ra)   = *(float4*)&As[kk][tr*8];
            *(float4*)(ra+4) = *(float4*)&As[kk][tr*8+4];
            *(float4*)(rb)   = *(float4*)&Bs[kk][tc*8];
            *(float4*)(rb+4) = *(float4*)&Bs[kk][tc*8+4];
            #pragma unroll
            for (int i = 0; i < 8; i++)
                #pragma unroll
                for (int jj = 0; jj < 8; jj++)
                    acc[i][jj] = fmaf(ra[i], rb[jj], acc[i][jj]);
        }
        __syncthreads();
    }
    // add bias, sumsq partials
    float bb[8];
    #pragma unroll
    for (int jj = 0; jj < 8; jj++) bb[jj] = bias[tc*8 + jj];
    #pragma unroll
    for (int i = 0; i < 8; i++) {
        float ssq = 0.f;
        #pragma unroll
        for (int jj = 0; jj < 8; jj++) {
            acc[i][jj] += bb[jj];
            ssq = fmaf(acc[i][jj], acc[i][jj], ssq);
        }
        red[tr*8+i][tc] = ssq;
    }
    __syncthreads();
    #pragma unroll
    for (int i = 0; i < 8; i++) {
        int row = tr*8 + i;
        float s = 0.f;
        #pragma unroll
        for (int t = 0; t < 16; t++) s += red[row][t];
        float r = 1.0f / fmaxf(sqrtf(s), 1e-12f);
        int gr = row0 + row;
        if (gr < NN) {
            float4 o0, o1;
            o0.x = acc[i][0]*r; o0.y = acc[i][1]*r; o0.z = acc[i][2]*r; o0.w = acc[i][3]*r;
            o1.x = acc[i][4]*r; o1.y = acc[i][5]*r; o1.z = acc[i][6]*r; o1.w = acc[i][7]*r;
            *(float4*)(C  + (size_t)gr*128 + tc*8)     = o0;
            *(float4*)(C  + (size_t)gr*128 + tc*8 + 4) = o1;
            *(float4*)(C2 + (size_t)gr*128 + tc*8)     = o0;
            *(float4*)(C2 + (size_t)gr*128 + tc*8 + 4) = o1;
        }
    }
}

// ============================ GAT aggregation (warp/node, 128-wide) ============================
__global__ __launch_bounds__(256) void k_gatagg(const float* __restrict__ attb)
{
    int node = blockIdx.x*8 + (threadIdx.x >> 5);
    if (node >= NN) return;
    int lane = threadIdx.x & 31;
    int e0 = g_off[node], e1 = g_off[node+1];
    float adb = g_adst[node] + attb[0];

    // segment max
    float mx = -FLT_MAX;
    for (int j = e0 + lane; j < e1; j += 32) {
        float e = g_asrc[g_csrc[j]] + adb;
        e = (e > 0.f) ? e : 0.01f*e;
        mx = fmaxf(mx, e);
    }
    #pragma unroll
    for (int o = 16; o > 0; o >>= 1) mx = fmaxf(mx, __shfl_xor_sync(0xffffffffu, mx, o));

    // weighted sum
    float4 acc = make_float4(0.f,0.f,0.f,0.f);
    float denom = 0.f;
    for (int base = e0; base < e1; base += 32) {
        int j = base + lane;
        int s = 0; float a = 0.f;
        if (j < e1) {
            s = g_csrc[j];
            float e = g_asrc[s] + adb;
            e = (e > 0.f) ? e : 0.01f*e;
            a = __expf(e - mx);
            denom += a;
        }
        int cnt = min(32, e1 - base);
        #pragma unroll 4
        for (int t = 0; t < cnt; t++) {
            float ab = __shfl_sync(0xffffffffu, a, t);
            int   sb = __shfl_sync(0xffffffffu, s, t);
            float4 v = *(const float4*)(g_m2 + (size_t)sb*DD + lane*4);
            acc.x = fmaf(ab, v.x, acc.x); acc.y = fmaf(ab, v.y, acc.y);
            acc.z = fmaf(ab, v.z, acc.z); acc.w = fmaf(ab, v.w, acc.w);
        }
    }
    #pragma unroll
    for (int o = 16; o > 0; o >>= 1) denom += __shfl_xor_sync(0xffffffffu, denom, o);
    float r = 1.0f / denom;
    acc.x *= r; acc.y *= r; acc.z *= r; acc.w *= r;
    *(float4*)(g_magg + (size_t)node*DD + lane*4) = acc;
}

// ============================ GEMM 64x256 + row-softmax epilogue -> s1 ============================
__global__ __launch_bounds__(256) void k_gemm_s1(float* __restrict__ s1out)
{
    __shared__ float As[8][64];
    __shared__ float Bs[8][256];
    __shared__ float red[64][16];
    int tid = threadIdx.x;
    int row0 = blockIdx.x*64;
    int tr = tid/16, tc = tid%16;   // rows tr*4..+3, cols tc*16..+15
    float acc[4][16];
    #pragma unroll
    for (int i = 0; i < 4; i++)
        #pragma unroll
        for (int jj = 0; jj < 16; jj++) acc[i][jj] = 0.f;

    int aRow = tid/4, aCol = (tid%4)*2;
    int bRow = tid/32, bCol = (tid%32)*8;

    for (int k0 = 0; k0 < 128; k0 += 8) {
        float2 av = make_float2(0.f,0.f);
        int gr = row0 + aRow;
        if (gr < NN) av = *(const float2*)(g_magg + (size_t)gr*128 + k0 + aCol);
        As[aCol+0][aRow] = av.x; As[aCol+1][aRow] = av.y;
        *(float4*)&Bs[bRow][bCol]   = *(const float4*)(g_Wcomb + (size_t)(k0+bRow)*256 + bCol);
        *(float4*)&Bs[bRow][bCol+4] = *(const float4*)(g_Wcomb + (size_t)(k0+bRow)*256 + bCol + 4);
        __syncthreads();
        #pragma unroll
        for (int kk = 0; kk < 8; kk++) {
            float ra[4], rb[16];
            *(float4*)(ra)    = *(float4*)&As[kk][tr*4];
            *(float4*)(rb)    = *(float4*)&Bs[kk][tc*16];
            *(float4*)(rb+4)  = *(float4*)&Bs[kk][tc*16+4];
            *(float4*)(rb+8)  = *(float4*)&Bs[kk][tc*16+8];
            *(float4*)(rb+12) = *(float4*)&Bs[kk][tc*16+12];
            #pragma unroll
            for (int i = 0; i < 4; i++)
                #pragma unroll
                for (int jj = 0; jj < 16; jj++)
                    acc[i][jj] = fmaf(ra[i], rb[jj], acc[i][jj]);
        }
        __syncthreads();
    }
    // bias + row softmax over 256 (16 tc-threads x 16 cols)
    float bb[16];
    #pragma unroll
    for (int jj = 0; jj < 16; jj++) bb[jj] = g_bcomb[tc*16 + jj];
    #pragma unroll
    for (int i = 0; i < 4; i++) {
        float lm = -FLT_MAX;
        #pragma unroll
        for (int jj = 0; jj < 16; jj++) {
            acc[i][jj] += bb[jj];
            lm = fmaxf(lm, acc[i][jj]);
        }
        red[tr*4+i][tc] = lm;
    }
    __syncthreads();
    float rowmax[4];
    #pragma unroll
    for (int i = 0; i < 4; i++) {
        float m = -FLT_MAX;
        #pragma unroll
        for (int t = 0; t < 16; t++) m = fmaxf(m, red[tr*4+i][t]);
        rowmax[i] = m;
    }
    __syncthreads();
    #pragma unroll
    for (int i = 0; i < 4; i++) {
        float ls = 0.f;
        #pragma unroll
        for (int jj = 0; jj < 16; jj++) {
            acc[i][jj] = __expf(acc[i][jj] - rowmax[i]);
            ls += acc[i][jj];
        }
        red[tr*4+i][tc] = ls;
    }
    __syncthreads();
    #pragma unroll
    for (int i = 0; i < 4; i++) {
        int gr = row0 + tr*4 + i;
        if (gr >= NN) continue;
        float s = 0.f;
        #pragma unroll
        for (int t = 0; t < 16; t++) s += red[tr*4+i][t];
        float rinv = 1.0f / s;
        #pragma unroll
        for (int jj = 0; jj < 16; jj += 4) {
            float4 o;
            o.x = acc[i][jj]*rinv; o.y = acc[i][jj+1]*rinv;
            o.z = acc[i][jj+2]*rinv; o.w = acc[i][jj+3]*rinv;
            *(float4*)(s1out + (size_t)gr*256 + tc*16 + jj) = o;
        }
    }
}

// ============================ T = s1^T @ m2 + colsum(s1) (split-K, atomic) ============================
#define SPLITS 80
__global__ __launch_bounds__(256) void k_at_b(const float* __restrict__ S)
{
    __shared__ float sS[16][64];
    __shared__ float sZ[16][128];
    int chunk = blockIdx.x;
    int k_begin = (int)((long long)NN * chunk / SPLITS);
    int k_end   = (int)((long long)NN * (chunk+1) / SPLITS);
    int m0 = blockIdx.y * 64;
    int tid = threadIdx.x;
    int tr = tid/16, tc = tid%16;
    float acc[4][8];
    #pragma unroll
    for (int i = 0; i < 4; i++)
        #pragma unroll
        for (int jj = 0; jj < 8; jj++) acc[i][jj] = 0.f;
    float colacc = 0.f;

    for (int k0 = k_begin; k0 < k_end; k0 += 16) {
        int kc = min(16, k_end - k0);
        {
            int r = tid/16, c4 = (tid%16)*4;
            float4 v = make_float4(0.f,0.f,0.f,0.f);
            if (r < kc) v = *(const float4*)(S + (size_t)(k0+r)*CC1 + m0 + c4);
            *(float4*)&sS[r][c4] = v;
        }
        #pragma unroll
        for (int half = 0; half < 2; half++) {
            int r = tid/32 + half*8, c4 = (tid%32)*4;
            float4 v = make_float4(0.f,0.f,0.f,0.f);
            if (r < kc) v = *(const float4*)(g_m2 + (size_t)(k0+r)*DD + c4);
            *(float4*)&sZ[r][c4] = v;
        }
        __syncthreads();
        if (tid < 64) {
            #pragma unroll
            for (int r = 0; r < 16; r++) colacc += sS[r][tid];
        }
        #pragma unroll
        for (int kk = 0; kk < 16; kk++) {
            float ra[4], rb[8];
            *(float4*)(ra)   = *(float4*)&sS[kk][tr*4];
            *(float4*)(rb)   = *(float4*)&sZ[kk][tc*8];
            *(float4*)(rb+4) = *(float4*)&sZ[kk][tc*8+4];
            #pragma unroll
            for (int i = 0; i < 4; i++)
                #pragma unroll
                for (int jj = 0; jj < 8; jj++)
                    acc[i][jj] = fmaf(ra[i], rb[jj], acc[i][jj]);
        }
        __syncthreads();
    }
    #pragma unroll
    for (int i = 0; i < 4; i++)
        #pragma unroll
        for (int jj = 0; jj < 8; jj++)
            atomicAdd(&g_T[(m0 + tr*4 + i)*DD + tc*8 + jj], acc[i][jj]);
    if (tid < 64) atomicAdd(&g_colsum[m0 + tid], colacc);
}

// ============================ x1 = T@We1 + colsum (x) be1 ============================
__global__ __launch_bounds__(256) void k_x1(
    const float* __restrict__ We1, const float* __restrict__ be1,
    float* __restrict__ out)
{
    int elem = blockIdx.x*256 + threadIdx.x;   // 32768 elems
    int k = elem >> 7, d = elem & 127;
    float s = 0.f;
    #pragma unroll 8
    for (int e = 0; e < 128; e++) s = fmaf(g_T[k*128 + e], We1[e*128 + d], s);
    out[OFF_X1 + elem] = s + g_colsum[k]*be1[d];
}

// ============================ analytic coarse tail ============================
__global__ __launch_bounds__(256) void k_tail(
    const float* __restrict__ We1, const float* __restrict__ be1,
    const float* __restrict__ We2, const float* __restrict__ be2,
    const float* __restrict__ Wa2, const float* __restrict__ ba2,
    float* __restrict__ out)
{
    __shared__ float sumT[128];
    __shared__ float meanx1[128];
    __shared__ float meanvec[128];
    __shared__ float s2row[32];
    __shared__ float sc[256];
    int t = threadIdx.x;

    if (t < 128) {
        float s = 0.f;
        for (int k = 0; k < 256; k++) s += g_T[k*128 + t];
        sumT[t] = s;
    }
    sc[t] = g_colsum[t];
    __syncthreads();
    #pragma unroll
    for (int st = 128; st > 0; st >>= 1) {
        if (t < st) sc[t] += sc[t+st];
        __syncthreads();
    }
    float sumcol = sc[0];
    if (t < 128) {
        float s = 0.f;
        for (int e = 0; e < 128; e++) s = fmaf(sumT[e], We1[e*128 + t], s);
        meanx1[t] = (s + sumcol*be1[t]) * (1.0f/256.0f);
    }
    __syncthreads();
    if (t < 128) {
        float s = 0.f;
        for (int e = 0; e < 128; e++) s = fmaf(meanx1[e], We2[e*128 + t], s);
        meanvec[t] = s + be2[t];
    }
    __syncthreads();
    if (t < 32) {
        float s = 0.f;
        for (int d = 0; d < 128; d++) s = fmaf(meanvec[d], Wa2[d*32 + t], s);
        float v = s + ba2[t];
        float mx = v;
        #pragma unroll
        for (int o = 16; o > 0; o >>= 1) mx = fmaxf(mx, __shfl_xor_sync(0xffffffffu, mx, o));
        float ex = __expf(v - mx);
        float sm = ex;
        #pragma unroll
        for (int o = 16; o > 0; o >>= 1) sm += __shfl_xor_sync(0xffffffffu, sm, o);
        s2row[t] = ex / sm;
    }
    __syncthreads();
    for (int i = t; i < 256*32; i += 256) out[OFF_S2 + i] = s2row[i & 31];
    if (t < 32) out[OFF_A1 + t] = 1.0f;
    for (int i = t; i < 32*128; i += 256)
        out[OFF_X2 + i] = 256.0f * s2row[i >> 7] * meanvec[i & 127];
    if (t == 0) {
        float s = 0.f;
        for (int d = 0; d < 128; d++) s += meanvec[d];
        out[OFF_E0] = s * (1.0f/16.0f);
    }
}

// ============================ launch ============================
extern "C" void kernel_launch(void* const* d_in, const int* in_sizes, int n_in,
                              void* d_out, int out_size)
{
    const float* feature = (const float*)d_in[0];
    const int*   eidx    = (const int*)d_in[1];
    const int*   src     = eidx;
    const int*   dst     = eidx + EE;
    const float* Wf   = (const float*)d_in[2];
    const float* bf   = (const float*)d_in[3];
    const float* We1  = (const float*)d_in[4];
    const float* be1  = (const float*)d_in[5];
    const float* Wa1  = (const float*)d_in[6];
    const float* ba1  = (const float*)d_in[7];
    const float* attW1 = (const float*)d_in[8];
    const float* attb1 = (const float*)d_in[9];
    const float* We2  = (const float*)d_in[10];
    const float* be2  = (const float*)d_in[11];
    const float* Wa2  = (const float*)d_in[12];
    const float* ba2  = (const float*)d_in[13];
    float* out = (float*)d_out;

    float *g_mf_p, *g_x_p, *g_m2_p;
    cudaGetSymbolAddress((void**)&g_mf_p, g_mf);
    cudaGetSymbolAddress((void**)&g_x_p, g_x);
    cudaGetSymbolAddress((void**)&g_m2_p, g_m2);

    // graph build + weight folding
    k_init<<<(CC1*DD + 255)/256, 256>>>();
    k_count<<<(EE + 255)/256, 256>>>(dst);
    k_fold<<<129, 256>>>(We1, be1, Wa1, ba1, attW1);
    k_scan<<<1, 1024>>>();
    k_fill<<<(EE + 255)/256, 256>>>(src, dst);

    // mf = segmean(feature)
    k_segmean<false,false><<<(NN+7)/8, 256>>>(feature, g_mf_p, (float*)0);
    // x = normalize(mf@Wf + bf); embed3 = x
    k_gemm_norm<<<(NN+127)/128, 256>>>(g_mf_p, Wf, bf, g_x_p, out + OFF_E3);
    // m2 = segmean(x) + fused a_src/a_dst
    k_segmean<false,true><<<(NN+7)/8, 256>>>(g_x_p, g_m2_p, (float*)0);
    // GAT aggregation on 128-wide m2
    k_gatagg<<<(NN+7)/8, 256>>>(attb1);
    // s1 = softmax(magg@W_comb + b_comb)
    k_gemm_s1<<<(NN+63)/64, 256>>>(out + OFF_S1);
    // T = s1^T @ m2, colsum(s1)
    k_at_b<<<dim3(SPLITS, 4), 256>>>(out + OFF_S1);
    // x1 = T@We1 + colsum (x) be1
    k_x1<<<128, 256>>>(We1, be1, out);
    // analytic coarse level
    k_tail<<<1, 256>>>(We1, be1, We2, be2, Wa2, ba2, out);
}